// round 1
// baseline (speedup 1.0000x reference)
#include <cuda_runtime.h>
#include <cstdint>
#include <cstddef>

// ---------------------------------------------------------------------------
// ChannelAttention: B=4, D=8, H=32, W=32, C=512, 8 heads x head_dim 64
//   xf (32768 x 512)
//   qkv = xf @ Wqkv^T                      (32768 x 1536)
//   per (b,h): attn = softmax(SCALE * K^T V)   (64 x 64)
//   out_h = Q @ attn^T                     (8192 x 64) per (b,h)
//   y = out @ Wproj^T + bproj              (32768 x 512)
// ---------------------------------------------------------------------------

static constexpr int kBatch    = 4;
static constexpr int kTok      = 8192;          // D*H*W
static constexpr int kC        = 512;
static constexpr int kHeads    = 8;
static constexpr int kHD       = 64;
static constexpr int kM        = kBatch * kTok; // 32768
static constexpr int kQKVld    = 3 * kC;        // 1536
static constexpr int kBH       = kBatch * kHeads; // 32
static constexpr int kChunks   = 16;
static constexpr int kChunkTok = kTok / kChunks;  // 512
static constexpr float kScale  = 0.125f;          // 64^-0.5

// Scratch (device globals; every element rewritten each launch -> graph-safe)
__device__ float g_qkv [(size_t)kM * kQKVld];                 // 192 MB
__device__ float g_part[(size_t)kBH * kChunks * kHD * kHD];   // 8 MB
__device__ float g_attn[(size_t)kBH * kHD * kHD];             // 0.5 MB
__device__ float g_outa[(size_t)kM * kC];                     // 64 MB

// ---------------------------------------------------------------------------
// Generic C = A @ B^T (+bias), A:(M,K) row-major lda, B:(N,K) row-major ldb.
// Tile 128x128x16, 256 threads, 8x8 per thread.
// Requires M%128==0, N%128==0, K%16==0, lda/ldb/ldc %4==0 (all true here).
// ---------------------------------------------------------------------------
__global__ __launch_bounds__(256) void gemm_abT(
    const float* __restrict__ A, int lda,
    const float* __restrict__ B, int ldb,
    const float* __restrict__ bias,
    float* __restrict__ C, int ldc,
    int K)
{
    __shared__ float As[16][128];
    __shared__ float Bs[16][128];

    const int tid = threadIdx.x;
    const int m0  = blockIdx.y * 128;
    const int n0  = blockIdx.x * 128;
    const int ty  = tid >> 4;   // 0..15 -> rows ty*8..+8
    const int tx  = tid & 15;   // 0..15 -> cols tx*8..+8

    const int ldRow = tid >> 1;        // 0..127
    const int ldK   = (tid & 1) * 8;   // 0 or 8

    const float* Aptr = A + (size_t)(m0 + ldRow) * lda + ldK;
    const float* Bptr = B + (size_t)(n0 + ldRow) * ldb + ldK;

    float acc[8][8];
    #pragma unroll
    for (int i = 0; i < 8; i++)
        #pragma unroll
        for (int j = 0; j < 8; j++)
            acc[i][j] = 0.f;

    for (int k0 = 0; k0 < K; k0 += 16) {
        float4 a0 = *(const float4*)(Aptr + k0);
        float4 a1 = *(const float4*)(Aptr + k0 + 4);
        float4 b0 = *(const float4*)(Bptr + k0);
        float4 b1 = *(const float4*)(Bptr + k0 + 4);

        __syncthreads();   // protect previous iteration's smem reads
        As[ldK+0][ldRow] = a0.x; As[ldK+1][ldRow] = a0.y;
        As[ldK+2][ldRow] = a0.z; As[ldK+3][ldRow] = a0.w;
        As[ldK+4][ldRow] = a1.x; As[ldK+5][ldRow] = a1.y;
        As[ldK+6][ldRow] = a1.z; As[ldK+7][ldRow] = a1.w;
        Bs[ldK+0][ldRow] = b0.x; Bs[ldK+1][ldRow] = b0.y;
        Bs[ldK+2][ldRow] = b0.z; Bs[ldK+3][ldRow] = b0.w;
        Bs[ldK+4][ldRow] = b1.x; Bs[ldK+5][ldRow] = b1.y;
        Bs[ldK+6][ldRow] = b1.z; Bs[ldK+7][ldRow] = b1.w;
        __syncthreads();

        #pragma unroll
        for (int kk = 0; kk < 16; kk++) {
            float4 ar0 = *(const float4*)&As[kk][ty * 8];
            float4 ar1 = *(const float4*)&As[kk][ty * 8 + 4];
            float4 br0 = *(const float4*)&Bs[kk][tx * 8];
            float4 br1 = *(const float4*)&Bs[kk][tx * 8 + 4];
            float a[8] = {ar0.x, ar0.y, ar0.z, ar0.w, ar1.x, ar1.y, ar1.z, ar1.w};
            float b[8] = {br0.x, br0.y, br0.z, br0.w, br1.x, br1.y, br1.z, br1.w};
            #pragma unroll
            for (int i = 0; i < 8; i++)
                #pragma unroll
                for (int j = 0; j < 8; j++)
                    acc[i][j] += a[i] * b[j];
        }
    }

    float bv[8];
    #pragma unroll
    for (int j = 0; j < 8; j++)
        bv[j] = bias ? bias[n0 + tx * 8 + j] : 0.f;

    #pragma unroll
    for (int i = 0; i < 8; i++) {
        float* crow = C + (size_t)(m0 + ty * 8 + i) * ldc + n0 + tx * 8;
        float4 o0, o1;
        o0.x = acc[i][0] + bv[0]; o0.y = acc[i][1] + bv[1];
        o0.z = acc[i][2] + bv[2]; o0.w = acc[i][3] + bv[3];
        o1.x = acc[i][4] + bv[4]; o1.y = acc[i][5] + bv[5];
        o1.z = acc[i][6] + bv[6]; o1.w = acc[i][7] + bv[7];
        *(float4*)(crow)     = o0;
        *(float4*)(crow + 4) = o1;
    }
}

// ---------------------------------------------------------------------------
// Partial K^T V: grid (chunk 0..15, bh 0..31). Each block reduces 512 tokens
// into a 64x64 partial written to g_part[bh][chunk][d][e] (un-scaled).
// ---------------------------------------------------------------------------
__global__ __launch_bounds__(256) void ktv_partial(
    const float* __restrict__ qkv, float* __restrict__ part)
{
    const int chunk = blockIdx.x;
    const int bh    = blockIdx.y;
    const int b = bh >> 3, h = bh & 7;

    __shared__ float ks[16][64];
    __shared__ float vs[16][64];

    const int tid = threadIdx.x;
    const int ty = tid >> 4;   // d block: ty*4..+4
    const int tx = tid & 15;   // e block: tx*4..+4

    const int lRow = tid >> 4;        // 0..15
    const int lCol = (tid & 15) * 4;  // 0..60

    const float* base  = qkv + (size_t)(b * kTok + chunk * kChunkTok) * kQKVld + h * kHD;
    const float* kbase = base + kC;        // K at +512
    const float* vbase = base + 2 * kC;    // V at +1024

    float acc[4][4];
    #pragma unroll
    for (int i = 0; i < 4; i++)
        #pragma unroll
        for (int j = 0; j < 4; j++)
            acc[i][j] = 0.f;

    for (int t0 = 0; t0 < kChunkTok; t0 += 16) {
        float4 kv = *(const float4*)(kbase + (size_t)(t0 + lRow) * kQKVld + lCol);
        float4 vv = *(const float4*)(vbase + (size_t)(t0 + lRow) * kQKVld + lCol);
        __syncthreads();
        *(float4*)&ks[lRow][lCol] = kv;
        *(float4*)&vs[lRow][lCol] = vv;
        __syncthreads();

        #pragma unroll
        for (int kk = 0; kk < 16; kk++) {
            float4 ka = *(const float4*)&ks[kk][ty * 4];
            float4 va = *(const float4*)&vs[kk][tx * 4];
            float a[4] = {ka.x, ka.y, ka.z, ka.w};
            float v[4] = {va.x, va.y, va.z, va.w};
            #pragma unroll
            for (int i = 0; i < 4; i++)
                #pragma unroll
                for (int j = 0; j < 4; j++)
                    acc[i][j] += a[i] * v[j];
        }
    }

    float* p = part + ((size_t)(bh * kChunks + chunk)) * kHD * kHD;
    #pragma unroll
    for (int i = 0; i < 4; i++) {
        float4 o;
        o.x = acc[i][0]; o.y = acc[i][1]; o.z = acc[i][2]; o.w = acc[i][3];
        *(float4*)(p + (ty * 4 + i) * kHD + tx * 4) = o;
    }
}

// ---------------------------------------------------------------------------
// Reduce partials, apply SCALE, row softmax over e. One block per bh.
// 8 warps x 8 rows each; lane handles e=lane and e=lane+32.
// ---------------------------------------------------------------------------
__global__ __launch_bounds__(256) void softmax_attn(
    const float* __restrict__ part, float* __restrict__ attn)
{
    const int bh   = blockIdx.x;
    const int warp = threadIdx.x >> 5;
    const int lane = threadIdx.x & 31;

    for (int r = 0; r < 8; r++) {
        const int d = warp * 8 + r;
        float v1 = 0.f, v2 = 0.f;
        for (int c = 0; c < kChunks; c++) {
            const float* row = part + ((size_t)(bh * kChunks + c) * kHD + d) * kHD;
            v1 += row[lane];
            v2 += row[lane + 32];
        }
        v1 *= kScale; v2 *= kScale;
        float m = fmaxf(v1, v2);
        #pragma unroll
        for (int s = 16; s > 0; s >>= 1)
            m = fmaxf(m, __shfl_xor_sync(0xffffffffu, m, s));
        float e1 = expf(v1 - m);
        float e2 = expf(v2 - m);
        float sm = e1 + e2;
        #pragma unroll
        for (int s = 16; s > 0; s >>= 1)
            sm += __shfl_xor_sync(0xffffffffu, sm, s);
        float inv = 1.f / sm;
        float* arow = attn + ((size_t)bh * kHD + d) * kHD;
        arow[lane]      = e1 * inv;
        arow[lane + 32] = e2 * inv;
    }
}

// ---------------------------------------------------------------------------
// out[n,d] = sum_e q[n,e] * attn[d,e], written into g_outa at (b,n, h*64+d).
// Grid (m-tile 0..63, bh 0..31). attn held transposed in smem.
// ---------------------------------------------------------------------------
__global__ __launch_bounds__(256) void q_attn(
    const float* __restrict__ qkv, const float* __restrict__ attn,
    float* __restrict__ outa)
{
    const int mt = blockIdx.x;  // 128 tokens per tile
    const int bh = blockIdx.y;
    const int b = bh >> 3, h = bh & 7;

    __shared__ float at[64][68];   // at[e][d], padded row (272B, 16B-aligned)
    __shared__ float qs[16][128];  // qs[e][m]

    const int tid = threadIdx.x;
    const int ty = tid >> 4;   // token rows ty*8..+8
    const int tx = tid & 15;   // d cols tx*4..+4

    const float* ag = attn + (size_t)bh * kHD * kHD;
    for (int i = tid; i < kHD * kHD; i += 256) {
        int d = i >> 6, e = i & 63;
        at[e][d] = ag[i];
    }

    const int lRow = tid >> 1;        // token 0..127
    const int lK   = (tid & 1) * 8;   // e offset 0 or 8
    const float* qbase = qkv + ((size_t)(b * kTok + mt * 128 + lRow)) * kQKVld
                             + h * kHD + lK;

    float acc[8][4];
    #pragma unroll
    for (int i = 0; i < 8; i++)
        #pragma unroll
        for (int j = 0; j < 4; j++)
            acc[i][j] = 0.f;

    for (int e0 = 0; e0 < kHD; e0 += 16) {
        float4 q0 = *(const float4*)(qbase + e0);
        float4 q1 = *(const float4*)(qbase + e0 + 4);
        __syncthreads();   // also covers the at[] stores on first iteration
        qs[lK+0][lRow] = q0.x; qs[lK+1][lRow] = q0.y;
        qs[lK+2][lRow] = q0.z; qs[lK+3][lRow] = q0.w;
        qs[lK+4][lRow] = q1.x; qs[lK+5][lRow] = q1.y;
        qs[lK+6][lRow] = q1.z; qs[lK+7][lRow] = q1.w;
        __syncthreads();

        #pragma unroll
        for (int kk = 0; kk < 16; kk++) {
            const int e = e0 + kk;
            float4 a0 = *(const float4*)&qs[kk][ty * 8];
            float4 a1 = *(const float4*)&qs[kk][ty * 8 + 4];
            float4 bv = *(const float4*)&at[e][tx * 4];
            float a[8] = {a0.x, a0.y, a0.z, a0.w, a1.x, a1.y, a1.z, a1.w};
            float bb[4] = {bv.x, bv.y, bv.z, bv.w};
            #pragma unroll
            for (int i = 0; i < 8; i++)
                #pragma unroll
                for (int j = 0; j < 4; j++)
                    acc[i][j] += a[i] * bb[j];
        }
    }

    #pragma unroll
    for (int i = 0; i < 8; i++) {
        const int m = mt * 128 + ty * 8 + i;
        float4 o;
        o.x = acc[i][0]; o.y = acc[i][1]; o.z = acc[i][2]; o.w = acc[i][3];
        *(float4*)(outa + ((size_t)(b * kTok + m)) * kC + h * kHD + tx * 4) = o;
    }
}

// ---------------------------------------------------------------------------
extern "C" void kernel_launch(void* const* d_in, const int* in_sizes, int n_in,
                              void* d_out, int out_size)
{
    const float* x     = (const float*)d_in[0];
    const float* Wqkv  = (const float*)d_in[1];
    const float* Wproj = (const float*)d_in[2];
    const float* bproj = (const float*)d_in[3];
    float* out = (float*)d_out;

    float *qkv, *part, *attn, *outa;
    cudaGetSymbolAddress((void**)&qkv,  g_qkv);
    cudaGetSymbolAddress((void**)&part, g_part);
    cudaGetSymbolAddress((void**)&attn, g_attn);
    cudaGetSymbolAddress((void**)&outa, g_outa);

    // 1) qkv = x @ Wqkv^T   (32768 x 1536, K=512)
    gemm_abT<<<dim3(kQKVld / 128, kM / 128), 256>>>(
        x, kC, Wqkv, kC, nullptr, qkv, kQKVld, kC);

    // 2) partial K^T V over 16 token chunks
    ktv_partial<<<dim3(kChunks, kBH), 256>>>(qkv, part);

    // 3) reduce + scale + softmax
    softmax_attn<<<kBH, 256>>>(part, attn);

    // 4) out_h = Q @ attn^T
    q_attn<<<dim3(kTok / 128, kBH), 256>>>(qkv, attn, outa);

    // 5) y = out @ Wproj^T + bproj   (32768 x 512, K=512)
    gemm_abT<<<dim3(kC / 128, kM / 128), 256>>>(
        outa, kC, Wproj, kC, bproj, out, kC, kC);
}

// round 3
// speedup vs baseline: 2.1863x; 2.1863x over previous
#include <cuda_runtime.h>
#include <cuda_bf16.h>
#include <cstdint>
#include <cstddef>

// ---------------------------------------------------------------------------
// ChannelAttention: B=4, D=8, H=32, W=32, C=512, 8 heads x head_dim 64
//   qkv = xf @ Wqkv^T           (32768 x 1536)   <- bf16x3 tensor-core GEMM
//   attn = softmax(SCALE K^T V) (64 x 64 per b,h) <- FFMA (small)
//   out_h = Q @ attn^T          (8192 x 64 per b,h) <- FFMA (for now)
//   y = out @ Wproj^T + bproj   (32768 x 512)    <- bf16x3 tensor-core GEMM
// ---------------------------------------------------------------------------

static constexpr int kBatch    = 4;
static constexpr int kTok      = 8192;
static constexpr int kC        = 512;
static constexpr int kHD       = 64;
static constexpr int kM        = kBatch * kTok;     // 32768
static constexpr int kQKVld    = 3 * kC;            // 1536
static constexpr int kBH       = kBatch * 8;        // 32
static constexpr int kChunks   = 16;
static constexpr int kChunkTok = kTok / kChunks;    // 512
static constexpr float kScale  = 0.125f;

// Scratch (device globals; fully rewritten each launch -> graph-safe)
__device__ float g_qkv [(size_t)kM * kQKVld];
__device__ float g_part[(size_t)kBH * kChunks * kHD * kHD];
__device__ float g_attn[(size_t)kBH * kHD * kHD];
__device__ float g_outa[(size_t)kM * kC];

// ---------------------------------------------------------------------------
// bf16x3 helpers
// ---------------------------------------------------------------------------
__device__ __forceinline__ void split8(const float4& u, const float4& v,
                                       uint4& hi, uint4& lo)
{
    float f[8] = {u.x, u.y, u.z, u.w, v.x, v.y, v.z, v.w};
    uint32_t h[4], l[4];
#pragma unroll
    for (int i = 0; i < 4; i++) {
        float a = f[2 * i], b = f[2 * i + 1];
        __nv_bfloat16 ah = __float2bfloat16_rn(a);
        __nv_bfloat16 bh = __float2bfloat16_rn(b);
        __nv_bfloat16 al = __float2bfloat16_rn(a - __bfloat162float(ah));
        __nv_bfloat16 bl = __float2bfloat16_rn(b - __bfloat162float(bh));
        __nv_bfloat162 ph; ph.x = ah; ph.y = bh;
        __nv_bfloat162 pl; pl.x = al; pl.y = bl;
        h[i] = *reinterpret_cast<uint32_t*>(&ph);
        l[i] = *reinterpret_cast<uint32_t*>(&pl);
    }
    hi.x = h[0]; hi.y = h[1]; hi.z = h[2]; hi.w = h[3];
    lo.x = l[0]; lo.y = l[1]; lo.z = l[2]; lo.w = l[3];
}

__device__ __forceinline__ void ldsm_x4(uint32_t addr, uint32_t* r)
{
    asm volatile("ldmatrix.sync.aligned.m8n8.x4.shared.b16 {%0,%1,%2,%3}, [%4];\n"
                 : "=r"(r[0]), "=r"(r[1]), "=r"(r[2]), "=r"(r[3])
                 : "r"(addr));
}

__device__ __forceinline__ void mma16816(float* c, const uint32_t* a,
                                         uint32_t b0, uint32_t b1)
{
    asm volatile(
        "mma.sync.aligned.m16n8k16.row.col.f32.bf16.bf16.f32 "
        "{%0,%1,%2,%3}, {%4,%5,%6,%7}, {%8,%9}, {%0,%1,%2,%3};\n"
        : "+f"(c[0]), "+f"(c[1]), "+f"(c[2]), "+f"(c[3])
        : "r"(a[0]), "r"(a[1]), "r"(a[2]), "r"(a[3]), "r"(b0), "r"(b1));
}

// ---------------------------------------------------------------------------
// C = A @ B^T (+bias) via bf16x3 mma.sync. A:(M,K) row-major lda, B:(N,K) ldb.
// Block tile 128x128, BK=16, 256 threads (8 warps of 32x64), double-buffered.
// Requires M%128==0, N%128==0, K%32==0.
// ---------------------------------------------------------------------------
static constexpr int kPad = 24;  // bf16 stride per smem row (48 B, conflict-free)

__global__ __launch_bounds__(256) void gemm_tc(
    const float* __restrict__ A, int lda,
    const float* __restrict__ B, int ldb,
    const float* __restrict__ bias,
    float* __restrict__ C, int ldc, int K)
{
    __shared__ __align__(16) __nv_bfloat16 As[2][2][128][kPad];
    __shared__ __align__(16) __nv_bfloat16 Bs[2][2][128][kPad];

    const int tid  = threadIdx.x;
    const int wid  = tid >> 5;
    const int lane = tid & 31;
    const int m0 = blockIdx.y * 128;
    const int n0 = blockIdx.x * 128;
    const int wm = (wid >> 1) * 32;   // warp M offset within block
    const int wn = (wid & 1) * 64;    // warp N offset within block

    // global fp32 load mapping: each thread 8 A floats + 8 B floats per tile
    const int grow = tid >> 1;         // 0..127
    const int gk   = (tid & 1) * 8;    // 0 or 8
    const float* Ag = A + (size_t)(m0 + grow) * lda + gk;
    const float* Bg = B + (size_t)(n0 + grow) * ldb + gk;

    // ldmatrix source mapping (per-lane)
    const int aRow = lane & 15;
    const int aKof = (lane >> 4) * 8;
    const int bRow = (lane & 7) + ((lane >> 4) & 1) * 8;
    const int bKof = ((lane >> 3) & 1) * 8;

    float acc[2][8][4];
#pragma unroll
    for (int mt = 0; mt < 2; mt++)
#pragma unroll
        for (int nt = 0; nt < 8; nt++)
#pragma unroll
            for (int i = 0; i < 4; i++)
                acc[mt][nt][i] = 0.f;

    float4 ra0, ra1, rb0, rb1;

    const int NK = K / 16;

    // prologue: tile 0 -> stage 0, prefetch tile 1 into registers
    ra0 = *(const float4*)(Ag);     ra1 = *(const float4*)(Ag + 4);
    rb0 = *(const float4*)(Bg);     rb1 = *(const float4*)(Bg + 4);
    {
        uint4 h, l;
        split8(ra0, ra1, h, l);
        *(uint4*)&As[0][0][grow][gk] = h;
        *(uint4*)&As[0][1][grow][gk] = l;
        split8(rb0, rb1, h, l);
        *(uint4*)&Bs[0][0][grow][gk] = h;
        *(uint4*)&Bs[0][1][grow][gk] = l;
    }
    if (NK > 1) {
        ra0 = *(const float4*)(Ag + 16);  ra1 = *(const float4*)(Ag + 20);
        rb0 = *(const float4*)(Bg + 16);  rb1 = *(const float4*)(Bg + 20);
    }
    __syncthreads();

#pragma unroll 1
    for (int kt = 0; kt < NK; kt++) {
        const int cur = kt & 1;

        if (kt + 1 < NK) {
            uint4 h, l;
            split8(ra0, ra1, h, l);
            *(uint4*)&As[cur ^ 1][0][grow][gk] = h;
            *(uint4*)&As[cur ^ 1][1][grow][gk] = l;
            split8(rb0, rb1, h, l);
            *(uint4*)&Bs[cur ^ 1][0][grow][gk] = h;
            *(uint4*)&Bs[cur ^ 1][1][grow][gk] = l;
        }
        if (kt + 2 < NK) {
            const float* ap = Ag + (kt + 2) * 16;
            const float* bp = Bg + (kt + 2) * 16;
            ra0 = *(const float4*)(ap);     ra1 = *(const float4*)(ap + 4);
            rb0 = *(const float4*)(bp);     rb1 = *(const float4*)(bp + 4);
        }

        // ---- compute on stage `cur` ----
        uint32_t ahi[2][4], alo[2][4];
#pragma unroll
        for (int mt = 0; mt < 2; mt++) {
            uint32_t aH = (uint32_t)__cvta_generic_to_shared(
                &As[cur][0][wm + mt * 16 + aRow][aKof]);
            uint32_t aL = (uint32_t)__cvta_generic_to_shared(
                &As[cur][1][wm + mt * 16 + aRow][aKof]);
            ldsm_x4(aH, ahi[mt]);
            ldsm_x4(aL, alo[mt]);
        }
#pragma unroll
        for (int ng = 0; ng < 4; ng++) {
            uint32_t bh[4], bl[4];
            uint32_t bH = (uint32_t)__cvta_generic_to_shared(
                &Bs[cur][0][wn + ng * 16 + bRow][bKof]);
            uint32_t bL = (uint32_t)__cvta_generic_to_shared(
                &Bs[cur][1][wn + ng * 16 + bRow][bKof]);
            ldsm_x4(bH, bh);
            ldsm_x4(bL, bl);
#pragma unroll
            for (int mt = 0; mt < 2; mt++) {
#pragma unroll
                for (int j = 0; j < 2; j++) {
                    float* c = acc[mt][ng * 2 + j];
                    mma16816(c, ahi[mt], bh[2 * j], bh[2 * j + 1]);  // hi*hi
                    mma16816(c, ahi[mt], bl[2 * j], bl[2 * j + 1]);  // hi*lo
                    mma16816(c, alo[mt], bh[2 * j], bh[2 * j + 1]);  // lo*hi
                }
            }
        }
        __syncthreads();
    }

    // epilogue
    const int g  = lane >> 2;
    const int tg = lane & 3;
#pragma unroll
    for (int mt = 0; mt < 2; mt++) {
#pragma unroll
        for (int nt = 0; nt < 8; nt++) {
            const int r   = m0 + wm + mt * 16 + g;
            const int col = n0 + wn + nt * 8 + tg * 2;
            float b0 = bias ? bias[col]     : 0.f;
            float b1 = bias ? bias[col + 1] : 0.f;
            float2 o0, o1;
            o0.x = acc[mt][nt][0] + b0; o0.y = acc[mt][nt][1] + b1;
            o1.x = acc[mt][nt][2] + b0; o1.y = acc[mt][nt][3] + b1;
            *(float2*)(C + (size_t)r * ldc + col)       = o0;
            *(float2*)(C + (size_t)(r + 8) * ldc + col) = o1;
        }
    }
}

// ---------------------------------------------------------------------------
// Partial K^T V: grid (chunk, bh). 512 tokens -> 64x64 partial (un-scaled).
// ---------------------------------------------------------------------------
__global__ __launch_bounds__(256) void ktv_partial(
    const float* __restrict__ qkv, float* __restrict__ part)
{
    const int chunk = blockIdx.x;
    const int bh    = blockIdx.y;
    const int b = bh >> 3, h = bh & 7;

    __shared__ float ks[16][64];
    __shared__ float vs[16][64];

    const int tid = threadIdx.x;
    const int ty = tid >> 4;
    const int tx = tid & 15;
    const int lRow = tid >> 4;
    const int lCol = (tid & 15) * 4;

    const float* base  = qkv + (size_t)(b * kTok + chunk * kChunkTok) * kQKVld + h * kHD;
    const float* kbase = base + kC;
    const float* vbase = base + 2 * kC;

    float acc[4][4];
#pragma unroll
    for (int i = 0; i < 4; i++)
#pragma unroll
        for (int j = 0; j < 4; j++)
            acc[i][j] = 0.f;

    for (int t0 = 0; t0 < kChunkTok; t0 += 16) {
        float4 kv = *(const float4*)(kbase + (size_t)(t0 + lRow) * kQKVld + lCol);
        float4 vv = *(const float4*)(vbase + (size_t)(t0 + lRow) * kQKVld + lCol);
        __syncthreads();
        *(float4*)&ks[lRow][lCol] = kv;
        *(float4*)&vs[lRow][lCol] = vv;
        __syncthreads();

#pragma unroll
        for (int kk = 0; kk < 16; kk++) {
            float4 ka = *(const float4*)&ks[kk][ty * 4];
            float4 va = *(const float4*)&vs[kk][tx * 4];
            float a[4] = {ka.x, ka.y, ka.z, ka.w};
            float v[4] = {va.x, va.y, va.z, va.w};
#pragma unroll
            for (int i = 0; i < 4; i++)
#pragma unroll
                for (int j = 0; j < 4; j++)
                    acc[i][j] += a[i] * v[j];
        }
    }

    float* p = part + ((size_t)(bh * kChunks + chunk)) * kHD * kHD;
#pragma unroll
    for (int i = 0; i < 4; i++) {
        float4 o;
        o.x = acc[i][0]; o.y = acc[i][1]; o.z = acc[i][2]; o.w = acc[i][3];
        *(float4*)(p + (ty * 4 + i) * kHD + tx * 4) = o;
    }
}

// ---------------------------------------------------------------------------
__global__ __launch_bounds__(256) void softmax_attn(
    const float* __restrict__ part, float* __restrict__ attn)
{
    const int bh   = blockIdx.x;
    const int warp = threadIdx.x >> 5;
    const int lane = threadIdx.x & 31;

    for (int r = 0; r < 8; r++) {
        const int d = warp * 8 + r;
        float v1 = 0.f, v2 = 0.f;
        for (int c = 0; c < kChunks; c++) {
            const float* row = part + ((size_t)(bh * kChunks + c) * kHD + d) * kHD;
            v1 += row[lane];
            v2 += row[lane + 32];
        }
        v1 *= kScale; v2 *= kScale;
        float m = fmaxf(v1, v2);
#pragma unroll
        for (int s = 16; s > 0; s >>= 1)
            m = fmaxf(m, __shfl_xor_sync(0xffffffffu, m, s));
        float e1 = expf(v1 - m);
        float e2 = expf(v2 - m);
        float sm = e1 + e2;
#pragma unroll
        for (int s = 16; s > 0; s >>= 1)
            sm += __shfl_xor_sync(0xffffffffu, sm, s);
        float inv = 1.f / sm;
        float* arow = attn + ((size_t)bh * kHD + d) * kHD;
        arow[lane]      = e1 * inv;
        arow[lane + 32] = e2 * inv;
    }
}

// ---------------------------------------------------------------------------
__global__ __launch_bounds__(256) void q_attn(
    const float* __restrict__ qkv, const float* __restrict__ attn,
    float* __restrict__ outa)
{
    const int mt = blockIdx.x;
    const int bh = blockIdx.y;
    const int b = bh >> 3, h = bh & 7;

    __shared__ float at[64][68];
    __shared__ float qs[16][128];

    const int tid = threadIdx.x;
    const int ty = tid >> 4;
    const int tx = tid & 15;

    const float* ag = attn + (size_t)bh * kHD * kHD;
    for (int i = tid; i < kHD * kHD; i += 256) {
        int d = i >> 6, e = i & 63;
        at[e][d] = ag[i];
    }

    const int lRow = tid >> 1;
    const int lK   = (tid & 1) * 8;
    const float* qbase = qkv + ((size_t)(b * kTok + mt * 128 + lRow)) * kQKVld
                             + h * kHD + lK;

    float acc[8][4];
#pragma unroll
    for (int i = 0; i < 8; i++)
#pragma unroll
        for (int j = 0; j < 4; j++)
            acc[i][j] = 0.f;

    for (int e0 = 0; e0 < kHD; e0 += 16) {
        float4 q0 = *(const float4*)(qbase + e0);
        float4 q1 = *(const float4*)(qbase + e0 + 4);
        __syncthreads();
        qs[lK+0][lRow] = q0.x; qs[lK+1][lRow] = q0.y;
        qs[lK+2][lRow] = q0.z; qs[lK+3][lRow] = q0.w;
        qs[lK+4][lRow] = q1.x; qs[lK+5][lRow] = q1.y;
        qs[lK+6][lRow] = q1.z; qs[lK+7][lRow] = q1.w;
        __syncthreads();

#pragma unroll
        for (int kk = 0; kk < 16; kk++) {
            const int e = e0 + kk;
            float4 a0 = *(const float4*)&qs[kk][ty * 8];
            float4 a1 = *(const float4*)&qs[kk][ty * 8 + 4];
            float4 bv = *(const float4*)&at[e][tx * 4];
            float a[8] = {a0.x, a0.y, a0.z, a0.w, a1.x, a1.y, a1.z, a1.w};
            float bb[4] = {bv.x, bv.y, bv.z, bv.w};
#pragma unroll
            for (int i = 0; i < 8; i++)
#pragma unroll
                for (int j = 0; j < 4; j++)
                    acc[i][j] += a[i] * bb[j];
        }
    }

#pragma unroll
    for (int i = 0; i < 8; i++) {
        const int m = mt * 128 + ty * 8 + i;
        float4 o;
        o.x = acc[i][0]; o.y = acc[i][1]; o.z = acc[i][2]; o.w = acc[i][3];
        *(float4*)(outa + ((size_t)(b * kTok + m)) * kC + h * kHD + tx * 4) = o;
    }
}

// ---------------------------------------------------------------------------
extern "C" void kernel_launch(void* const* d_in, const int* in_sizes, int n_in,
                              void* d_out, int out_size)
{
    const float* x     = (const float*)d_in[0];
    const float* Wqkv  = (const float*)d_in[1];
    const float* Wproj = (const float*)d_in[2];
    const float* bproj = (const float*)d_in[3];
    float* out = (float*)d_out;

    float *qkv, *part, *attn, *outa;
    cudaGetSymbolAddress((void**)&qkv,  g_qkv);
    cudaGetSymbolAddress((void**)&part, g_part);
    cudaGetSymbolAddress((void**)&attn, g_attn);
    cudaGetSymbolAddress((void**)&outa, g_outa);

    // 1) qkv = x @ Wqkv^T   (32768 x 1536, K=512)  [tensor core bf16x3]
    gemm_tc<<<dim3(kQKVld / 128, kM / 128), 256>>>(
        x, kC, Wqkv, kC, nullptr, qkv, kQKVld, kC);

    // 2) partial K^T V over 16 token chunks
    ktv_partial<<<dim3(kChunks, kBH), 256>>>(qkv, part);

    // 3) reduce + scale + softmax
    softmax_attn<<<kBH, 256>>>(part, attn);

    // 4) out_h = Q @ attn^T
    q_attn<<<dim3(kTok / 128, kBH), 256>>>(qkv, attn, outa);

    // 5) y = out @ Wproj^T + bproj   (32768 x 512, K=512) [tensor core bf16x3]
    gemm_tc<<<dim3(kC / 128, kM / 128), 256>>>(
        outa, kC, Wproj, kC, bproj, out, kC, kC);
}